// round 5
// baseline (speedup 1.0000x reference)
#include <cuda_runtime.h>

// ---------------- static problem sizes ----------------
#define N_NODES 20000
#define E_EDGES 320000
#define B_Q 4
#define K_T 32
#define D_DIM 32
#define DR_REL 40
#define T_STEPS 10
#define VTH 2.0f
#define DECAY 0.7788007830714049f   // exp(-1/4)
#define RATIO 0.95f
#define NSCALE 8.025261215232422f   // (1 - 0.95^10) / (1 - 0.95)

#define NTHR 256
#define NW 8                         // warps per block

// ---------------- persistent state (zero-init; cleanup restores zeros) ----------------
__device__ unsigned g_smask[T_STEPS * N_NODES * B_Q];   // sparse-touched
__device__ float    g_v[N_NODES * B_Q * D_DIM];         // sparse-touched
__device__ float    g_c[N_NODES * B_Q * D_DIM];         // sparse-touched
__device__ float    g_agg[N_NODES * B_Q * D_DIM];       // sparse-touched
__device__ int      g_hot_flag[N_NODES];
__device__ int      g_hot_list[N_NODES];
__device__ float    g_wrel[B_Q * DR_REL * D_DIM];       // lazily (re)computed

__global__ __launch_bounds__(NTHR, 1)
void fused_kernel(const int* __restrict__ edge_src,
                  const int* __restrict__ edge_dst,
                  const int* __restrict__ edge_type,
                  const int* __restrict__ h_index,
                  const int* __restrict__ t_index,
                  const int* __restrict__ r_index,
                  const float* __restrict__ query_emb,
                  const float* __restrict__ relw_W,
                  const float* __restrict__ relw_b,
                  const float* __restrict__ lin_W,
                  const float* __restrict__ lin_b,
                  const float* __restrict__ W1,
                  const float* __restrict__ b1,
                  const float* __restrict__ W2,
                  const float* __restrict__ b2,
                  float* __restrict__ out) {
    __shared__ float s_WT[D_DIM * D_DIM];       // s_WT[i*32+j] = lin_W[j*32+i]
    __shared__ float s_W1t[64 * 64];            // s_W1t[i*64+j] = W1[j*64+i]  (i-major)
    __shared__ float s_b1[64], s_W2[64];
    __shared__ float s_q[B_Q * D_DIM];
    __shared__ float s_b2;
    __shared__ int   s_hot_count, s_front_prev, s_front_cur, s_wrel_done;

    const int tid  = threadIdx.x;
    const int lane = tid & 31;
    const int warp = tid >> 5;

    // ---------- phase 0: load weights to shared, init head nodes ----------
    for (int i = tid; i < D_DIM * D_DIM; i += NTHR) {
        int ii = i >> 5, j = i & 31;
        s_WT[i] = lin_W[j * D_DIM + ii];
    }
    for (int idx = tid; idx < 64 * 64; idx += NTHR) {
        int i = idx >> 6, j = idx & 63;
        s_W1t[idx] = W1[j * 64 + i];
    }
    if (tid < 64) { s_b1[tid] = b1[tid]; s_W2[tid] = W2[tid]; }
    if (tid < B_Q * D_DIM)
        s_q[tid] = query_emb[r_index[tid >> 5] * D_DIM + (tid & 31)];
    if (tid == 0) {
        s_b2 = b2[0];
        s_hot_count = 0; s_front_prev = 0; s_front_cur = 0; s_wrel_done = 0;
    }
    __syncthreads();

    if (warp < B_Q) {        // head-node init: warp b
        int b = warp;
        int n = h_index[b];
        float q = s_q[b * D_DIM + lane];
        float boundary = q * (VTH * 0.5f) + VTH * 0.5f;
        bool sp = (boundary - VTH) >= 0.f;
        g_v[(n * B_Q + b) * D_DIM + lane] = sp ? 0.f : boundary;
        unsigned m = __ballot_sync(0xffffffffu, sp);
        if (lane == 0) {
            g_smask[n * B_Q + b] = m;
            if (m) atomicAdd(&s_front_prev, 1);
            if (atomicExch(&g_hot_flag[n], 1) == 0) {
                int p = atomicAdd(&s_hot_count, 1);
                g_hot_list[p] = n;
            }
        }
    }
    __syncthreads();

    // ---------- time loop ----------
    const float lb = __ldg(lin_b + lane);
    for (int t = 1; t < T_STEPS; ++t) {
        int fc = s_front_prev;     // block-uniform (post-sync)
        if (fc != 0) {
            // lazy relation-weight projection (only needed when messages flow)
            if (!s_wrel_done) {
                for (int id = tid; id < B_Q * DR_REL * D_DIM; id += NTHR) {
                    int b  = id / (DR_REL * D_DIM);
                    int rd = id % (DR_REL * D_DIM);
                    float acc = relw_b[rd];
#pragma unroll
                    for (int i = 0; i < D_DIM; ++i)
                        acc += s_q[b * D_DIM + i] * relw_W[i * (DR_REL * D_DIM) + rd];
                    g_wrel[id] = acc;
                }
                __syncthreads();
                if (tid == 0) s_wrel_done = 1;
            }
            // edge-parallel scatter (generic slow path; gated off when frontier empty)
            const unsigned* mp = g_smask + (size_t)(t - 1) * (N_NODES * B_Q);
            for (int e = warp; e < E_EDGES; e += NW) {
                int src = __ldg(edge_src + e);
                uint4 m = *reinterpret_cast<const uint4*>(mp + src * 4);
                if (m.x | m.y | m.z | m.w) {
                    int dst = __ldg(edge_dst + e);
                    int ty  = __ldg(edge_type + e);
                    if (lane == 0) {
                        if (atomicExch(&g_hot_flag[dst], 1) == 0) {
                            int p = atomicAdd(&s_hot_count, 1);
                            g_hot_list[p] = dst;
                        }
                    }
                    int off = ty * D_DIM + lane;
                    float* ag = g_agg + (size_t)(dst * B_Q) * D_DIM + lane;
                    if ((m.x >> lane) & 1u) atomicAdd(ag + 0 * D_DIM, g_wrel[0 * DR_REL * D_DIM + off]);
                    if ((m.y >> lane) & 1u) atomicAdd(ag + 1 * D_DIM, g_wrel[1 * DR_REL * D_DIM + off]);
                    if ((m.z >> lane) & 1u) atomicAdd(ag + 2 * D_DIM, g_wrel[2 * DR_REL * D_DIM + off]);
                    if ((m.w >> lane) & 1u) atomicAdd(ag + 3 * D_DIM, g_wrel[3 * DR_REL * D_DIM + off]);
                }
            }
            __syncthreads();
        }

        // LIF update over hot list
        int nh = s_hot_count;
        for (int i = warp; i < nh; i += NW) {
            int n = g_hot_list[i];
            size_t base = (size_t)(n * B_Q) * D_DIM + lane;
            float a0 = 0.f, a1 = 0.f, a2 = 0.f, a3 = 0.f;
            if (fc != 0) {
                a0 = g_agg[base + 0 * D_DIM]; g_agg[base + 0 * D_DIM] = 0.f;
                a1 = g_agg[base + 1 * D_DIM]; g_agg[base + 1 * D_DIM] = 0.f;
                a2 = g_agg[base + 2 * D_DIM]; g_agg[base + 2 * D_DIM] = 0.f;
                a3 = g_agg[base + 3 * D_DIM]; g_agg[base + 3 * D_DIM] = 0.f;
            }
            float x0 = lb, x1 = lb, x2 = lb, x3 = lb;
#pragma unroll
            for (int k = 0; k < D_DIM; ++k) {
                float w = s_WT[k * D_DIM + lane];
                x0 = fmaf(__shfl_sync(0xffffffffu, a0, k), w, x0);
                x1 = fmaf(__shfl_sync(0xffffffffu, a1, k), w, x1);
                x2 = fmaf(__shfl_sync(0xffffffffu, a2, k), w, x2);
                x3 = fmaf(__shfl_sync(0xffffffffu, a3, k), w, x3);
            }
            unsigned bm[4];
            float xs[4] = {x0, x1, x2, x3};
#pragma unroll
            for (int b = 0; b < B_Q; ++b) {
                float c = g_c[base + b * D_DIM] * DECAY + xs[b];
                float v = g_v[base + b * D_DIM] * DECAY + c;
                bool sp = (v - VTH) >= 0.f;
                g_c[base + b * D_DIM] = c;
                g_v[base + b * D_DIM] = sp ? 0.f : v;
                bm[b] = __ballot_sync(0xffffffffu, sp);
            }
            if (lane == 0) {
                *reinterpret_cast<uint4*>(g_smask + (size_t)t * (N_NODES * B_Q) + n * B_Q) =
                    make_uint4(bm[0], bm[1], bm[2], bm[3]);
                if (bm[0] | bm[1] | bm[2] | bm[3]) atomicAdd(&s_front_cur, 1);
            }
        }
        __syncthreads();
        if (tid == 0) { s_front_prev = s_front_cur; s_front_cur = 0; }
        __syncthreads();
    }

    // ---------- score: warp per (b,k) pair, 16 rounds ----------
    for (int p = warp; p < B_Q * K_T; p += NW) {
        int b = p >> 5;            // / K_T
        int k = p & 31;
        int tn = __ldg(t_index + b * K_T + k);
        // feat[lane] = enc, feat[32+lane] = query
        float e = 0.f, w = 1.0f;
#pragma unroll
        for (int t = 0; t < T_STEPS; ++t) {
            unsigned m = g_smask[(size_t)t * (N_NODES * B_Q) + tn * B_Q + b];
            if ((m >> lane) & 1u) e += w;
            w *= RATIO;
        }
        float f0 = e / NSCALE;
        float f1 = s_q[b * D_DIM + lane];
        // hidden rows lane and lane+32
        float acc0 = s_b1[lane], acc1 = s_b1[lane + 32];
#pragma unroll
        for (int i = 0; i < 32; ++i) {
            float a = __shfl_sync(0xffffffffu, f0, i);
            float c = __shfl_sync(0xffffffffu, f1, i);
            acc0 = fmaf(a, s_W1t[i * 64 + lane],             acc0);
            acc0 = fmaf(c, s_W1t[(i + 32) * 64 + lane],      acc0);
            acc1 = fmaf(a, s_W1t[i * 64 + lane + 32],        acc1);
            acc1 = fmaf(c, s_W1t[(i + 32) * 64 + lane + 32], acc1);
        }
        float h = fmaxf(acc0, 0.f) * s_W2[lane] + fmaxf(acc1, 0.f) * s_W2[lane + 32];
#pragma unroll
        for (int off = 16; off; off >>= 1)
            h += __shfl_down_sync(0xffffffffu, h, off);
        if (lane == 0) out[p] = h + s_b2;
    }
    __syncthreads();   // score reads must finish before cleanup clobbers state

    // ---------- cleanup: restore pristine zeros for next replay ----------
    {
        int nh = s_hot_count;
        for (int i = warp; i < nh; i += NW) {
            int n = g_hot_list[i];
            size_t base = (size_t)(n * B_Q) * D_DIM + lane;
#pragma unroll
            for (int b = 0; b < B_Q; ++b) {
                g_v[base + b * D_DIM]   = 0.f;
                g_c[base + b * D_DIM]   = 0.f;
                g_agg[base + b * D_DIM] = 0.f;
            }
            if (lane < T_STEPS)
                *reinterpret_cast<uint4*>(g_smask + (size_t)lane * (N_NODES * B_Q) + n * B_Q) =
                    make_uint4(0u, 0u, 0u, 0u);
            if (lane == 0) g_hot_flag[n] = 0;
        }
    }
}

// ---------------- launch ----------------
extern "C" void kernel_launch(void* const* d_in, const int* in_sizes, int n_in,
                              void* d_out, int out_size) {
    fused_kernel<<<1, NTHR>>>(
        (const int*)d_in[0], (const int*)d_in[1], (const int*)d_in[2],
        (const int*)d_in[3], (const int*)d_in[4], (const int*)d_in[5],
        (const float*)d_in[6], (const float*)d_in[7], (const float*)d_in[8],
        (const float*)d_in[9], (const float*)d_in[10],
        (const float*)d_in[11], (const float*)d_in[12],
        (const float*)d_in[13], (const float*)d_in[14],
        (float*)d_out);
}

// round 6
// speedup vs baseline: 2.7191x; 2.7191x over previous
#include <cuda_runtime.h>

// ---------------- static problem sizes ----------------
#define N_NODES 20000
#define E_EDGES 320000
#define B_Q 4
#define K_T 32
#define D_DIM 32
#define DR_REL 40
#define T_STEPS 10
#define VTH 2.0f
#define DECAY 0.7788007830714049f   // exp(-1/4)
#define RATIO 0.95f
#define NSCALE 8.025261215232422f   // (1 - 0.95^10) / (1 - 0.95)

#define NBLKS 16
#define NTHR 256
#define NW 8                         // warps per block

// ---------------- persistent state (zero-init; cleanup restores zeros) ----------------
__device__ unsigned g_smask[T_STEPS * N_NODES * B_Q];   // sparse-touched
__device__ float    g_v[N_NODES * B_Q * D_DIM];         // sparse-touched
__device__ float    g_c[N_NODES * B_Q * D_DIM];         // sparse-touched
__device__ float    g_agg[N_NODES * B_Q * D_DIM];       // sparse-touched
__device__ int      g_hot_flag[N_NODES];
__device__ int      g_hot_list[N_NODES];
__device__ int      g_hot_count;
__device__ float    g_wrel[B_Q * DR_REL * D_DIM];       // lazily computed (slow path only)
__device__ int      g_sim_done;                         // 0 at launch; reset by cleanup
__device__ int      g_score_done;                       // arrival counter; reset by cleanup

__global__ __launch_bounds__(NTHR, 1)
void fused_kernel(const int* __restrict__ edge_src,
                  const int* __restrict__ edge_dst,
                  const int* __restrict__ edge_type,
                  const int* __restrict__ h_index,
                  const int* __restrict__ t_index,
                  const int* __restrict__ r_index,
                  const float* __restrict__ query_emb,
                  const float* __restrict__ relw_W,
                  const float* __restrict__ relw_b,
                  const float* __restrict__ lin_W,
                  const float* __restrict__ lin_b,
                  const float* __restrict__ W1,
                  const float* __restrict__ b1,
                  const float* __restrict__ W2,
                  const float* __restrict__ b2,
                  float* __restrict__ out) {
    __shared__ float s_W1t[64 * 64];     // s_W1t[i*64+j] = W1[j*64+i]
    __shared__ float s_lin[64 * 65];     // padded staging for conflict-free transpose
    __shared__ float s_q[B_Q * D_DIM];
    __shared__ float s_b1[64], s_W2[64];
    __shared__ float s_b2s;
    __shared__ float s_WT[D_DIM * D_DIM];   // block 0: lin_W transposed
    __shared__ int   s_hot, s_fprev, s_fcur, s_ts, s_wrel_done, s_rank;

    const int tid  = threadIdx.x;
    const int lane = tid & 31;
    const int warp = tid >> 5;
    const int bid  = blockIdx.x;

    // ---------- common preload (coalesced) ----------
    for (int idx = tid; idx < 64 * 64; idx += NTHR) {
        int j = idx >> 6, i = idx & 63;
        s_lin[j * 65 + i] = W1[idx];             // coalesced global read
    }
    if (tid < 64) { s_b1[tid] = b1[tid]; s_W2[tid] = W2[tid]; }
    if (tid < B_Q * D_DIM)
        s_q[tid] = query_emb[r_index[tid >> 5] * D_DIM + (tid & 31)];
    if (tid == 0) s_b2s = b2[0];
    __syncthreads();
    for (int idx = tid; idx < 64 * 64; idx += NTHR) {
        int i = idx >> 6, j = idx & 63;
        s_W1t[idx] = s_lin[j * 65 + i];          // conflict-free shared transpose
    }

    // ================= block 0: simulation =================
    if (bid == 0) {
        for (int i = tid; i < D_DIM * D_DIM; i += NTHR) {
            int ii = i >> 5, j = i & 31;
            s_WT[i] = lin_W[j * D_DIM + ii];
        }
        if (tid == 0) { s_hot = 0; s_fprev = 0; s_fcur = 0; s_ts = T_STEPS; s_wrel_done = 0; }
        __syncthreads();

        // ---- init head nodes (warp b) ----
        if (warp < B_Q) {
            int b = warp;
            int n = h_index[b];
            float q = s_q[b * D_DIM + lane];
            float boundary = q * (VTH * 0.5f) + VTH * 0.5f;
            bool sp = (boundary - VTH) >= 0.f;
            g_v[(n * B_Q + b) * D_DIM + lane] = sp ? 0.f : boundary;
            unsigned m = __ballot_sync(0xffffffffu, sp);
            if (lane == 0) {
                g_smask[n * B_Q + b] = m;
                if (m) atomicAdd(&s_fprev, 1);
                if (atomicExch(&g_hot_flag[n], 1) == 0) {
                    int p = atomicAdd(&s_hot, 1);
                    g_hot_list[p] = n;
                }
            }
        }
        __syncthreads();

        int t_start = 1;
        if (s_fprev == 0) {
            // ---- fast path: frontier empty -> independent decay, registers only ----
            int nh = s_hot;
            int myts = T_STEPS;
            for (int i = warp; i < nh; i += NW) {
                int n = g_hot_list[i];
                size_t base = (size_t)(n * B_Q) * D_DIM + lane;
                float v[4], c[4];
#pragma unroll
                for (int b = 0; b < B_Q; ++b) { v[b] = g_v[base + b * D_DIM]; c[b] = g_c[base + b * D_DIM]; }
                for (int t = 1; t < T_STEPS; ++t) {
                    unsigned any = 0;
#pragma unroll
                    for (int b = 0; b < B_Q; ++b) {
                        c[b] *= DECAY;
                        v[b] = v[b] * DECAY + c[b];
                        any |= __ballot_sync(0xffffffffu, (v[b] - VTH) >= 0.f);
                    }
                    if (any) { if (t < myts) myts = t; break; }
                }
            }
            if (lane == 0) atomicMin(&s_ts, myts);
            __syncthreads();
            int ts = s_ts;
            if (ts < T_STEPS) {
                // roll all hot nodes to ts, write state + masks, count frontier
                for (int i = warp; i < nh; i += NW) {
                    int n = g_hot_list[i];
                    size_t base = (size_t)(n * B_Q) * D_DIM + lane;
                    float v[4], c[4];
                    unsigned bm[4] = {0u, 0u, 0u, 0u};
#pragma unroll
                    for (int b = 0; b < B_Q; ++b) { v[b] = g_v[base + b * D_DIM]; c[b] = g_c[base + b * D_DIM]; }
                    for (int t = 1; t <= ts; ++t) {
#pragma unroll
                        for (int b = 0; b < B_Q; ++b) {
                            c[b] *= DECAY;
                            v[b] = v[b] * DECAY + c[b];
                            if (t == ts) {
                                bool sp = (v[b] - VTH) >= 0.f;
                                bm[b] = __ballot_sync(0xffffffffu, sp);
                                if (sp) v[b] = 0.f;
                            }
                        }
                    }
#pragma unroll
                    for (int b = 0; b < B_Q; ++b) { g_v[base + b * D_DIM] = v[b]; g_c[base + b * D_DIM] = c[b]; }
                    if (lane == 0) {
                        *reinterpret_cast<uint4*>(g_smask + (size_t)ts * (N_NODES * B_Q) + n * B_Q) =
                            make_uint4(bm[0], bm[1], bm[2], bm[3]);
                        if (bm[0] | bm[1] | bm[2] | bm[3]) atomicAdd(&s_fprev, 1);
                    }
                }
                t_start = ts + 1;
            } else {
                t_start = T_STEPS;   // no spikes ever: smask stays pristine zero
            }
            __syncthreads();
        }

        // ---- generic loop (only runs if spikes exist) ----
        const float lb = __ldg(lin_b + lane);
        for (int t = t_start; t < T_STEPS; ++t) {
            int fc = s_fprev;
            if (fc != 0) {
                if (!s_wrel_done) {
                    for (int id = tid; id < B_Q * DR_REL * D_DIM; id += NTHR) {
                        int b  = id / (DR_REL * D_DIM);
                        int rd = id % (DR_REL * D_DIM);
                        float acc = relw_b[rd];
#pragma unroll
                        for (int i = 0; i < D_DIM; ++i)
                            acc += s_q[b * D_DIM + i] * relw_W[i * (DR_REL * D_DIM) + rd];
                        g_wrel[id] = acc;
                    }
                    __syncthreads();
                    if (tid == 0) s_wrel_done = 1;
                }
                const unsigned* mp = g_smask + (size_t)(t - 1) * (N_NODES * B_Q);
                for (int e = warp; e < E_EDGES; e += NW) {
                    int src = __ldg(edge_src + e);
                    uint4 m = *reinterpret_cast<const uint4*>(mp + src * 4);
                    if (m.x | m.y | m.z | m.w) {
                        int dst = __ldg(edge_dst + e);
                        int ty  = __ldg(edge_type + e);
                        if (lane == 0) {
                            if (atomicExch(&g_hot_flag[dst], 1) == 0) {
                                int p = atomicAdd(&s_hot, 1);
                                g_hot_list[p] = dst;
                            }
                        }
                        int off = ty * D_DIM + lane;
                        float* ag = g_agg + (size_t)(dst * B_Q) * D_DIM + lane;
                        if ((m.x >> lane) & 1u) atomicAdd(ag + 0 * D_DIM, g_wrel[0 * DR_REL * D_DIM + off]);
                        if ((m.y >> lane) & 1u) atomicAdd(ag + 1 * D_DIM, g_wrel[1 * DR_REL * D_DIM + off]);
                        if ((m.z >> lane) & 1u) atomicAdd(ag + 2 * D_DIM, g_wrel[2 * DR_REL * D_DIM + off]);
                        if ((m.w >> lane) & 1u) atomicAdd(ag + 3 * D_DIM, g_wrel[3 * DR_REL * D_DIM + off]);
                    }
                }
                __syncthreads();
            }
            int nh = s_hot;
            for (int i = warp; i < nh; i += NW) {
                int n = g_hot_list[i];
                size_t base = (size_t)(n * B_Q) * D_DIM + lane;
                float a0 = 0.f, a1 = 0.f, a2 = 0.f, a3 = 0.f;
                if (fc != 0) {
                    a0 = g_agg[base + 0 * D_DIM]; g_agg[base + 0 * D_DIM] = 0.f;
                    a1 = g_agg[base + 1 * D_DIM]; g_agg[base + 1 * D_DIM] = 0.f;
                    a2 = g_agg[base + 2 * D_DIM]; g_agg[base + 2 * D_DIM] = 0.f;
                    a3 = g_agg[base + 3 * D_DIM]; g_agg[base + 3 * D_DIM] = 0.f;
                }
                float x0 = lb, x1 = lb, x2 = lb, x3 = lb;
#pragma unroll
                for (int k = 0; k < D_DIM; ++k) {
                    float w = s_WT[k * D_DIM + lane];
                    x0 = fmaf(__shfl_sync(0xffffffffu, a0, k), w, x0);
                    x1 = fmaf(__shfl_sync(0xffffffffu, a1, k), w, x1);
                    x2 = fmaf(__shfl_sync(0xffffffffu, a2, k), w, x2);
                    x3 = fmaf(__shfl_sync(0xffffffffu, a3, k), w, x3);
                }
                unsigned bm[4];
                float xs[4] = {x0, x1, x2, x3};
#pragma unroll
                for (int b = 0; b < B_Q; ++b) {
                    float c = g_c[base + b * D_DIM] * DECAY + xs[b];
                    float v = g_v[base + b * D_DIM] * DECAY + c;
                    bool sp = (v - VTH) >= 0.f;
                    g_c[base + b * D_DIM] = c;
                    g_v[base + b * D_DIM] = sp ? 0.f : v;
                    bm[b] = __ballot_sync(0xffffffffu, sp);
                }
                if (lane == 0) {
                    *reinterpret_cast<uint4*>(g_smask + (size_t)t * (N_NODES * B_Q) + n * B_Q) =
                        make_uint4(bm[0], bm[1], bm[2], bm[3]);
                    if (bm[0] | bm[1] | bm[2] | bm[3]) atomicAdd(&s_fcur, 1);
                }
            }
            __syncthreads();
            if (tid == 0) { s_fprev = s_fcur; s_fcur = 0; }
            __syncthreads();
        }

        // ---- publish sim results ----
        if (tid == 0) {
            g_hot_count = s_hot;
            __threadfence();
            atomicExch(&g_sim_done, 1);
        }
    }

    // ================= all blocks: wait for sim =================
    if (tid == 0) {
        while (atomicAdd(&g_sim_done, 0) == 0) __nanosleep(32);
    }
    __syncthreads();

    // ================= score: warp per (b,k) pair =================
    {
        int p = bid * NW + warp;             // 16 blocks * 8 warps = 128 pairs exactly
        int b = p >> 5;                      // K_T == 32
        int tn = __ldg(t_index + p);
        float e = 0.f, w = 1.0f;
#pragma unroll
        for (int t = 0; t < T_STEPS; ++t) {
            unsigned m = __ldcg(&g_smask[(size_t)t * (N_NODES * B_Q) + tn * B_Q + b]);
            if ((m >> lane) & 1u) e += w;
            w *= RATIO;
        }
        float f0 = e / NSCALE;
        float f1 = s_q[b * D_DIM + lane];
        float acc0 = s_b1[lane], acc1 = s_b1[lane + 32];
#pragma unroll
        for (int i = 0; i < 32; ++i) {
            float a = __shfl_sync(0xffffffffu, f0, i);
            float c = __shfl_sync(0xffffffffu, f1, i);
            acc0 = fmaf(a, s_W1t[i * 64 + lane],             acc0);
            acc0 = fmaf(c, s_W1t[(i + 32) * 64 + lane],      acc0);
            acc1 = fmaf(a, s_W1t[i * 64 + lane + 32],        acc1);
            acc1 = fmaf(c, s_W1t[(i + 32) * 64 + lane + 32], acc1);
        }
        float h = fmaxf(acc0, 0.f) * s_W2[lane] + fmaxf(acc1, 0.f) * s_W2[lane + 32];
#pragma unroll
        for (int off = 16; off; off >>= 1)
            h += __shfl_down_sync(0xffffffffu, h, off);
        if (lane == 0) out[p] = h + s_b2s;
    }
    __syncthreads();

    // ================= arrival; last block cleans up =================
    if (tid == 0) {
        __threadfence();                       // my smask reads & out writes done
        s_rank = atomicAdd(&g_score_done, 1);
    }
    __syncthreads();
    if (s_rank == NBLKS - 1) {
        int nh = g_hot_count;
        for (int i = warp; i < nh; i += NW) {
            int n = g_hot_list[i];
            size_t base = (size_t)(n * B_Q) * D_DIM + lane;
#pragma unroll
            for (int b = 0; b < B_Q; ++b) {
                g_v[base + b * D_DIM]   = 0.f;
                g_c[base + b * D_DIM]   = 0.f;
                g_agg[base + b * D_DIM] = 0.f;
            }
            if (lane < T_STEPS)
                *reinterpret_cast<uint4*>(g_smask + (size_t)lane * (N_NODES * B_Q) + n * B_Q) =
                    make_uint4(0u, 0u, 0u, 0u);
            if (lane == 0) g_hot_flag[n] = 0;
        }
        __syncthreads();
        if (tid == 0) {
            g_score_done = 0;
            __threadfence();
            atomicExch(&g_sim_done, 0);
        }
    }
}

// ---------------- launch ----------------
extern "C" void kernel_launch(void* const* d_in, const int* in_sizes, int n_in,
                              void* d_out, int out_size) {
    fused_kernel<<<NBLKS, NTHR>>>(
        (const int*)d_in[0], (const int*)d_in[1], (const int*)d_in[2],
        (const int*)d_in[3], (const int*)d_in[4], (const int*)d_in[5],
        (const float*)d_in[6], (const float*)d_in[7], (const float*)d_in[8],
        (const float*)d_in[9], (const float*)d_in[10],
        (const float*)d_in[11], (const float*)d_in[12],
        (const float*)d_in[13], (const float*)d_in[14],
        (float*)d_out);
}

// round 7
// speedup vs baseline: 4.0405x; 1.4860x over previous
#include <cuda_runtime.h>

// ---------------- static problem sizes ----------------
#define N_NODES 20000
#define E_EDGES 320000
#define B_Q 4
#define K_T 32
#define D_DIM 32
#define DR_REL 40
#define T_STEPS 10
#define VTH 2.0f
#define DECAY 0.7788007830714049f   // exp(-1/4)
#define RATIO 0.95f
#define NSCALE 8.025261215232422f   // (1 - 0.95^10) / (1 - 0.95)

#define NBLKS 16
#define NTHR 256
#define NW 8                         // warps per block

// ---------------- persistent state (zero-init; cleanup restores zeros) ----------------
__device__ unsigned g_smask[T_STEPS * N_NODES * B_Q];   // sparse-touched
__device__ float    g_v[N_NODES * B_Q * D_DIM];         // sparse-touched (slow path only)
__device__ float    g_c[N_NODES * B_Q * D_DIM];
__device__ float    g_agg[N_NODES * B_Q * D_DIM];
__device__ int      g_hot_flag[N_NODES];
__device__ int      g_hot_list[N_NODES];
__device__ int      g_hot_count;
__device__ float    g_wrel[B_Q * DR_REL * D_DIM];       // lazily computed (slow path only)
__device__ int      g_sim_done;    // 0=pending, 1=done/no-spikes, 2=done/spikes-present
__device__ int      g_score_done;  // arrival counter

__global__ __launch_bounds__(NTHR, 1)
void fused_kernel(const int* __restrict__ edge_src,
                  const int* __restrict__ edge_dst,
                  const int* __restrict__ edge_type,
                  const int* __restrict__ h_index,
                  const int* __restrict__ t_index,
                  const int* __restrict__ r_index,
                  const float* __restrict__ query_emb,
                  const float* __restrict__ relw_W,
                  const float* __restrict__ relw_b,
                  const float* __restrict__ lin_W,
                  const float* __restrict__ lin_b,
                  const float* __restrict__ W1,
                  const float* __restrict__ b1,
                  const float* __restrict__ W2,
                  const float* __restrict__ b2,
                  float* __restrict__ out) {
    __shared__ float s_W1[64 * 65];          // padded row-major W1 (conflict-free)
    __shared__ float s_WT[D_DIM * D_DIM];    // lin_W^T (block 0 slow path only)
    __shared__ float s_q[B_Q * D_DIM];
    __shared__ float s_b1[64], s_W2[64];
    __shared__ float s_b2s;
    __shared__ int   s_hot, s_fprev, s_fcur, s_ts, s_wrel_done, s_rank, s_flag;

    const int tid  = threadIdx.x;
    const int lane = tid & 31;
    const int warp = tid >> 5;
    const int bid  = blockIdx.x;

    // ---------- minimal prefix everyone needs before the fork ----------
    if (tid < B_Q * D_DIM)
        s_q[tid] = query_emb[__ldg(r_index + (tid >> 5)) * D_DIM + (tid & 31)];
    if (tid < 64) { s_b1[tid] = __ldg(b1 + tid); s_W2[tid] = __ldg(W2 + tid); }
    if (tid == 0) {
        s_b2s = __ldg(b2);
        s_hot = 0; s_fprev = 0; s_fcur = 0; s_ts = T_STEPS; s_wrel_done = 0;
    }
    __syncthreads();

    // ---------- W1 preload helper (runs at different times per block) ----------
    auto preload_W1 = [&]() {
        const float4* W14 = reinterpret_cast<const float4*>(W1);
#pragma unroll
        for (int q = 0; q < 4; ++q) {
            int idx4 = q * NTHR + tid;          // 1024 float4 total
            float4 v = __ldg(W14 + idx4);
            int j = idx4 >> 4, i = (idx4 & 15) << 2;
            float* dst = s_W1 + j * 65 + i;
            dst[0] = v.x; dst[1] = v.y; dst[2] = v.z; dst[3] = v.w;
        }
    };

    // ================= block 0: simulation =================
    if (bid == 0) {
        // ---- register-resident fast scan: no global writes unless a spike occurs ----
        if (warp < B_Q) {
            int b = warp;
            float q = s_q[b * D_DIM + lane];
            float boundary = q * (VTH * 0.5f) + VTH * 0.5f;
            unsigned m0 = __ballot_sync(0xffffffffu, (boundary - VTH) >= 0.f);
            int myts = T_STEPS;
            if (m0) {
                myts = 0;
            } else {
                float v = boundary, c = 0.f;
                for (int t = 1; t < T_STEPS; ++t) {
                    c *= DECAY;
                    v = v * DECAY + c;
                    if (__ballot_sync(0xffffffffu, (v - VTH) >= 0.f)) { myts = t; break; }
                }
            }
            if (lane == 0) atomicMin(&s_ts, myts);
        }
        __syncthreads();
        int ts = s_ts;

        if (ts < T_STEPS) {
            // ---- rare slow path: materialize state at ts, then generic sim ----
            if (warp < B_Q) {
                int b = warp;
                int n = __ldg(h_index + b);
                float q = s_q[b * D_DIM + lane];
                float boundary = q * (VTH * 0.5f) + VTH * 0.5f;
                float v = boundary, c = 0.f;
                unsigned bm;
                if (ts == 0) {
                    bool sp = (boundary - VTH) >= 0.f;
                    bm = __ballot_sync(0xffffffffu, sp);
                    if (sp) v = 0.f;
                } else {
                    for (int t = 1; t <= ts; ++t) { c *= DECAY; v = v * DECAY + c; }
                    bool sp = (v - VTH) >= 0.f;
                    bm = __ballot_sync(0xffffffffu, sp);
                    if (sp) v = 0.f;
                }
                size_t base = (size_t)(n * B_Q + b) * D_DIM + lane;
                g_v[base] = v;
                g_c[base] = c;
                if (lane == 0) {
                    if (bm) {
                        g_smask[(size_t)ts * (N_NODES * B_Q) + n * B_Q + b] = bm;
                        atomicAdd(&s_fprev, 1);
                    }
                    if (atomicExch(&g_hot_flag[n], 1) == 0) {
                        int p = atomicAdd(&s_hot, 1);
                        g_hot_list[p] = n;
                    }
                }
            }
            // lin_W^T for the generic linear
            for (int i = tid; i < D_DIM * D_DIM; i += NTHR) {
                int ii = i >> 5, j = i & 31;
                s_WT[i] = lin_W[j * D_DIM + ii];
            }
            __syncthreads();

            const float lb = __ldg(lin_b + lane);
            for (int t = ts + 1; t < T_STEPS; ++t) {
                int fc = s_fprev;
                if (fc != 0) {
                    if (!s_wrel_done) {
                        for (int id = tid; id < B_Q * DR_REL * D_DIM; id += NTHR) {
                            int b  = id / (DR_REL * D_DIM);
                            int rd = id % (DR_REL * D_DIM);
                            float acc = relw_b[rd];
#pragma unroll
                            for (int i = 0; i < D_DIM; ++i)
                                acc += s_q[b * D_DIM + i] * relw_W[i * (DR_REL * D_DIM) + rd];
                            g_wrel[id] = acc;
                        }
                        __syncthreads();
                        if (tid == 0) s_wrel_done = 1;
                    }
                    const unsigned* mp = g_smask + (size_t)(t - 1) * (N_NODES * B_Q);
                    for (int e = warp; e < E_EDGES; e += NW) {
                        int src = __ldg(edge_src + e);
                        uint4 m = *reinterpret_cast<const uint4*>(mp + src * 4);
                        if (m.x | m.y | m.z | m.w) {
                            int dst = __ldg(edge_dst + e);
                            int ty  = __ldg(edge_type + e);
                            if (lane == 0) {
                                if (atomicExch(&g_hot_flag[dst], 1) == 0) {
                                    int p = atomicAdd(&s_hot, 1);
                                    g_hot_list[p] = dst;
                                }
                            }
                            int off = ty * D_DIM + lane;
                            float* ag = g_agg + (size_t)(dst * B_Q) * D_DIM + lane;
                            if ((m.x >> lane) & 1u) atomicAdd(ag + 0 * D_DIM, g_wrel[0 * DR_REL * D_DIM + off]);
                            if ((m.y >> lane) & 1u) atomicAdd(ag + 1 * D_DIM, g_wrel[1 * DR_REL * D_DIM + off]);
                            if ((m.z >> lane) & 1u) atomicAdd(ag + 2 * D_DIM, g_wrel[2 * DR_REL * D_DIM + off]);
                            if ((m.w >> lane) & 1u) atomicAdd(ag + 3 * D_DIM, g_wrel[3 * DR_REL * D_DIM + off]);
                        }
                    }
                    __syncthreads();
                }
                int nh = s_hot;
                for (int i = warp; i < nh; i += NW) {
                    int n = g_hot_list[i];
                    size_t base = (size_t)(n * B_Q) * D_DIM + lane;
                    float a0 = 0.f, a1 = 0.f, a2 = 0.f, a3 = 0.f;
                    if (fc != 0) {
                        a0 = g_agg[base + 0 * D_DIM]; g_agg[base + 0 * D_DIM] = 0.f;
                        a1 = g_agg[base + 1 * D_DIM]; g_agg[base + 1 * D_DIM] = 0.f;
                        a2 = g_agg[base + 2 * D_DIM]; g_agg[base + 2 * D_DIM] = 0.f;
                        a3 = g_agg[base + 3 * D_DIM]; g_agg[base + 3 * D_DIM] = 0.f;
                    }
                    float x0 = lb, x1 = lb, x2 = lb, x3 = lb;
#pragma unroll
                    for (int k = 0; k < D_DIM; ++k) {
                        float w = s_WT[k * D_DIM + lane];
                        x0 = fmaf(__shfl_sync(0xffffffffu, a0, k), w, x0);
                        x1 = fmaf(__shfl_sync(0xffffffffu, a1, k), w, x1);
                        x2 = fmaf(__shfl_sync(0xffffffffu, a2, k), w, x2);
                        x3 = fmaf(__shfl_sync(0xffffffffu, a3, k), w, x3);
                    }
                    unsigned bm[4];
                    float xs[4] = {x0, x1, x2, x3};
#pragma unroll
                    for (int b = 0; b < B_Q; ++b) {
                        float c = g_c[base + b * D_DIM] * DECAY + xs[b];
                        float v = g_v[base + b * D_DIM] * DECAY + c;
                        bool sp = (v - VTH) >= 0.f;
                        g_c[base + b * D_DIM] = c;
                        g_v[base + b * D_DIM] = sp ? 0.f : v;
                        bm[b] = __ballot_sync(0xffffffffu, sp);
                    }
                    if (lane == 0) {
                        *reinterpret_cast<uint4*>(g_smask + (size_t)t * (N_NODES * B_Q) + n * B_Q) =
                            make_uint4(bm[0], bm[1], bm[2], bm[3]);
                        if (bm[0] | bm[1] | bm[2] | bm[3]) atomicAdd(&s_fcur, 1);
                    }
                }
                __syncthreads();
                if (tid == 0) { s_fprev = s_fcur; s_fcur = 0; }
                __syncthreads();
            }
        }

        // ---- publish ----
        if (tid == 0) {
            g_hot_count = s_hot;
            __threadfence();
            atomicExch(&g_sim_done, (ts < T_STEPS) ? 2 : 1);
        }
        preload_W1();                       // block 0 preloads after publishing
    } else {
        preload_W1();                       // other blocks preload while block 0 sims
    }

    // ================= wait for sim =================
    if (tid == 0) {
        int f;
        while ((f = atomicAdd(&g_sim_done, 0)) == 0) __nanosleep(32);
        s_flag = f;
    }
    __syncthreads();
    const int flag = s_flag;

    // ================= score: warp per (b,k) pair (16*8 = 128 exactly) =================
    {
        int p = bid * NW + warp;
        int b = p >> 5;                      // K_T == 32
        float e = 0.f;
        if (flag == 2) {                     // spikes exist somewhere: read masks
            int tn = __ldg(t_index + p);
            float w = 1.0f;
#pragma unroll
            for (int t = 0; t < T_STEPS; ++t) {
                unsigned m = __ldcg(&g_smask[(size_t)t * (N_NODES * B_Q) + tn * B_Q + b]);
                if ((m >> lane) & 1u) e += w;
                w *= RATIO;
            }
        }
        float f0 = e / NSCALE;
        float f1 = s_q[b * D_DIM + lane];
        float acc0 = s_b1[lane], acc1 = s_b1[lane + 32];
#pragma unroll
        for (int i = 0; i < 32; ++i) {
            float a = __shfl_sync(0xffffffffu, f0, i);
            float c = __shfl_sync(0xffffffffu, f1, i);
            acc0 = fmaf(a, s_W1[lane * 65 + i],              acc0);
            acc0 = fmaf(c, s_W1[lane * 65 + 32 + i],         acc0);
            acc1 = fmaf(a, s_W1[(lane + 32) * 65 + i],       acc1);
            acc1 = fmaf(c, s_W1[(lane + 32) * 65 + 32 + i],  acc1);
        }
        float h = fmaxf(acc0, 0.f) * s_W2[lane] + fmaxf(acc1, 0.f) * s_W2[lane + 32];
#pragma unroll
        for (int off = 16; off; off >>= 1)
            h += __shfl_down_sync(0xffffffffu, h, off);
        if (lane == 0) out[p] = h + s_b2s;
    }
    __syncthreads();

    // ================= arrival; last block cleans up =================
    if (tid == 0) {
        __threadfence();
        s_rank = atomicAdd(&g_score_done, 1);
    }
    __syncthreads();
    if (s_rank == NBLKS - 1) {
        int nh = g_hot_count;                // 0 on the fast path: loop is empty
        for (int i = warp; i < nh; i += NW) {
            int n = g_hot_list[i];
            size_t base = (size_t)(n * B_Q) * D_DIM + lane;
#pragma unroll
            for (int b = 0; b < B_Q; ++b) {
                g_v[base + b * D_DIM]   = 0.f;
                g_c[base + b * D_DIM]   = 0.f;
                g_agg[base + b * D_DIM] = 0.f;
            }
            if (lane < T_STEPS)
                *reinterpret_cast<uint4*>(g_smask + (size_t)lane * (N_NODES * B_Q) + n * B_Q) =
                    make_uint4(0u, 0u, 0u, 0u);
            if (lane == 0) g_hot_flag[n] = 0;
        }
        __syncthreads();
        if (tid == 0) {
            g_score_done = 0;
            __threadfence();
            atomicExch(&g_sim_done, 0);
        }
    }
}

// ---------------- launch ----------------
extern "C" void kernel_launch(void* const* d_in, const int* in_sizes, int n_in,
                              void* d_out, int out_size) {
    fused_kernel<<<NBLKS, NTHR>>>(
        (const int*)d_in[0], (const int*)d_in[1], (const int*)d_in[2],
        (const int*)d_in[3], (const int*)d_in[4], (const int*)d_in[5],
        (const float*)d_in[6], (const float*)d_in[7], (const float*)d_in[8],
        (const float*)d_in[9], (const float*)d_in[10],
        (const float*)d_in[11], (const float*)d_in[12],
        (const float*)d_in[13], (const float*)d_in[14],
        (float*)d_out);
}

// round 8
// speedup vs baseline: 5.8688x; 1.4525x over previous
#include <cuda_runtime.h>

// ---------------- static problem sizes ----------------
#define N_NODES 20000
#define E_EDGES 320000
#define B_Q 4
#define K_T 32
#define D_DIM 32
#define DR_REL 40
#define T_STEPS 10
#define VTH 2.0f
#define DECAY 0.7788007830714049f   // exp(-1/4)
#define RATIO 0.95f
#define NSCALE 8.025261215232422f   // (1 - 0.95^10) / (1 - 0.95)

#define NBLKS 16
#define NTHR 256
#define NW 8                         // warps per block

// ---------------- persistent state (zero-init; cleanup restores zeros) ----------------
// Fast path touches NONE of these (except reads of pristine zeros never happen).
__device__ unsigned g_smask[T_STEPS * N_NODES * B_Q];
__device__ float    g_v[N_NODES * B_Q * D_DIM];
__device__ float    g_c[N_NODES * B_Q * D_DIM];
__device__ float    g_agg[N_NODES * B_Q * D_DIM];
__device__ int      g_hot_flag[N_NODES];
__device__ int      g_hot_list[N_NODES];
__device__ int      g_hot_count;
__device__ float    g_wrel[B_Q * DR_REL * D_DIM];
__device__ int      g_sim_done;     // slow path only
__device__ int      g_score_done;   // slow path only

__global__ __launch_bounds__(NTHR, 1)
void fused_kernel(const int* __restrict__ edge_src,
                  const int* __restrict__ edge_dst,
                  const int* __restrict__ edge_type,
                  const int* __restrict__ h_index,
                  const int* __restrict__ t_index,
                  const int* __restrict__ r_index,
                  const float* __restrict__ query_emb,
                  const float* __restrict__ relw_W,
                  const float* __restrict__ relw_b,
                  const float* __restrict__ lin_W,
                  const float* __restrict__ lin_b,
                  const float* __restrict__ W1,
                  const float* __restrict__ b1,
                  const float* __restrict__ W2,
                  const float* __restrict__ b2,
                  float* __restrict__ out) {
    __shared__ float s_W1[64 * 65];          // padded row-major W1 (conflict-free)
    __shared__ float s_WT[D_DIM * D_DIM];    // lin_W^T (slow path only)
    __shared__ float s_q[B_Q * D_DIM];
    __shared__ float s_b1[64], s_W2[64];
    __shared__ float s_b2s;
    __shared__ int   s_ts, s_hot, s_fprev, s_fcur, s_wrel_done, s_rank;

    const int tid  = threadIdx.x;
    const int lane = tid & 31;
    const int warp = tid >> 5;
    const int bid  = blockIdx.x;

    // ---------- issue ALL global loads up front (maximize MLP) ----------
    const float4* W14 = reinterpret_cast<const float4*>(W1);
    float4 wv0 = __ldg(W14 + 0 * NTHR + tid);
    float4 wv1 = __ldg(W14 + 1 * NTHR + tid);
    float4 wv2 = __ldg(W14 + 2 * NTHR + tid);
    float4 wv3 = __ldg(W14 + 3 * NTHR + tid);
    float qv = 0.f, sc0 = 0.f, sc1 = 0.f, bb2 = 0.f;
    if (tid < B_Q * D_DIM)
        qv = __ldg(query_emb + __ldg(r_index + (tid >> 5)) * D_DIM + (tid & 31));
    if (tid < 64) { sc0 = __ldg(b1 + tid); sc1 = __ldg(W2 + tid); }
    if (tid == 0) bb2 = __ldg(b2);

    // ---------- stage into shared ----------
    {
        int i4 = tid << 2;                      // element index of wv0 block
        // idx4 = q*256+tid ; j = idx4>>4 ; i = (idx4&15)<<2
        float* d0 = s_W1 + ((0 * NTHR + tid) >> 4) * 65 + (((0 * NTHR + tid) & 15) << 2);
        float* d1 = s_W1 + ((1 * NTHR + tid) >> 4) * 65 + (((1 * NTHR + tid) & 15) << 2);
        float* d2 = s_W1 + ((2 * NTHR + tid) >> 4) * 65 + (((2 * NTHR + tid) & 15) << 2);
        float* d3 = s_W1 + ((3 * NTHR + tid) >> 4) * 65 + (((3 * NTHR + tid) & 15) << 2);
        d0[0] = wv0.x; d0[1] = wv0.y; d0[2] = wv0.z; d0[3] = wv0.w;
        d1[0] = wv1.x; d1[1] = wv1.y; d1[2] = wv1.z; d1[3] = wv1.w;
        d2[0] = wv2.x; d2[1] = wv2.y; d2[2] = wv2.z; d2[3] = wv2.w;
        d3[0] = wv3.x; d3[1] = wv3.y; d3[2] = wv3.z; d3[3] = wv3.w;
        (void)i4;
    }
    if (tid < B_Q * D_DIM) s_q[tid] = qv;
    if (tid < 64) { s_b1[tid] = sc0; s_W2[tid] = sc1; }
    if (tid == 0) {
        s_b2s = bb2;
        s_ts = T_STEPS; s_hot = 0; s_fprev = 0; s_fcur = 0; s_wrel_done = 0;
    }
    __syncthreads();

    // ---------- every block: register-resident first-spike scan ----------
    if (warp < B_Q) {
        float q = s_q[warp * D_DIM + lane];
        float boundary = q * (VTH * 0.5f) + VTH * 0.5f;
        int myts = T_STEPS;
        if (__ballot_sync(0xffffffffu, (boundary - VTH) >= 0.f)) {
            myts = 0;
        } else {
            float v = boundary, c = 0.f;
            for (int t = 1; t < T_STEPS; ++t) {
                c *= DECAY;
                v = v * DECAY + c;
                if (__ballot_sync(0xffffffffu, (v - VTH) >= 0.f)) { myts = t; break; }
            }
        }
        if (lane == 0 && myts < T_STEPS) atomicMin(&s_ts, myts);
    }
    __syncthreads();
    const int ts = s_ts;           // identical in every block (deterministic FP)

    bool read_masks = false;

    if (ts < T_STEPS) {
        // ======================= SLOW PATH (spikes exist) =======================
        read_masks = true;
        if (bid == 0) {
            // materialize head-node state at ts
            if (warp < B_Q) {
                int b = warp;
                int n = __ldg(h_index + b);
                float q = s_q[b * D_DIM + lane];
                float boundary = q * (VTH * 0.5f) + VTH * 0.5f;
                float v = boundary, c = 0.f;
                for (int t = 1; t <= ts; ++t) { c *= DECAY; v = v * DECAY + c; }
                bool sp = (v - VTH) >= 0.f;
                unsigned bm = __ballot_sync(0xffffffffu, sp);
                if (sp) v = 0.f;
                size_t base = (size_t)(n * B_Q + b) * D_DIM + lane;
                g_v[base] = v;
                g_c[base] = c;
                if (lane == 0) {
                    if (bm) {
                        g_smask[(size_t)ts * (N_NODES * B_Q) + n * B_Q + b] = bm;
                        atomicAdd(&s_fprev, 1);
                    }
                    if (atomicExch(&g_hot_flag[n], 1) == 0) {
                        int p = atomicAdd(&s_hot, 1);
                        g_hot_list[p] = n;
                    }
                }
            }
            for (int i = tid; i < D_DIM * D_DIM; i += NTHR) {
                int ii = i >> 5, j = i & 31;
                s_WT[i] = lin_W[j * D_DIM + ii];
            }
            __syncthreads();

            const float lb = __ldg(lin_b + lane);
            for (int t = ts + 1; t < T_STEPS; ++t) {
                int fc = s_fprev;
                if (fc != 0) {
                    if (!s_wrel_done) {
                        for (int id = tid; id < B_Q * DR_REL * D_DIM; id += NTHR) {
                            int b  = id / (DR_REL * D_DIM);
                            int rd = id % (DR_REL * D_DIM);
                            float acc = relw_b[rd];
#pragma unroll
                            for (int i = 0; i < D_DIM; ++i)
                                acc += s_q[b * D_DIM + i] * relw_W[i * (DR_REL * D_DIM) + rd];
                            g_wrel[id] = acc;
                        }
                        __syncthreads();
                        if (tid == 0) s_wrel_done = 1;
                    }
                    const unsigned* mp = g_smask + (size_t)(t - 1) * (N_NODES * B_Q);
                    for (int e = warp; e < E_EDGES; e += NW) {
                        int src = __ldg(edge_src + e);
                        uint4 m = *reinterpret_cast<const uint4*>(mp + src * 4);
                        if (m.x | m.y | m.z | m.w) {
                            int dst = __ldg(edge_dst + e);
                            int ty  = __ldg(edge_type + e);
                            if (lane == 0) {
                                if (atomicExch(&g_hot_flag[dst], 1) == 0) {
                                    int p = atomicAdd(&s_hot, 1);
                                    g_hot_list[p] = dst;
                                }
                            }
                            int off = ty * D_DIM + lane;
                            float* ag = g_agg + (size_t)(dst * B_Q) * D_DIM + lane;
                            if ((m.x >> lane) & 1u) atomicAdd(ag + 0 * D_DIM, g_wrel[0 * DR_REL * D_DIM + off]);
                            if ((m.y >> lane) & 1u) atomicAdd(ag + 1 * D_DIM, g_wrel[1 * DR_REL * D_DIM + off]);
                            if ((m.z >> lane) & 1u) atomicAdd(ag + 2 * D_DIM, g_wrel[2 * DR_REL * D_DIM + off]);
                            if ((m.w >> lane) & 1u) atomicAdd(ag + 3 * D_DIM, g_wrel[3 * DR_REL * D_DIM + off]);
                        }
                    }
                    __syncthreads();
                }
                int nh = s_hot;
                for (int i = warp; i < nh; i += NW) {
                    int n = g_hot_list[i];
                    size_t base = (size_t)(n * B_Q) * D_DIM + lane;
                    float a0 = 0.f, a1 = 0.f, a2 = 0.f, a3 = 0.f;
                    if (fc != 0) {
                        a0 = g_agg[base + 0 * D_DIM]; g_agg[base + 0 * D_DIM] = 0.f;
                        a1 = g_agg[base + 1 * D_DIM]; g_agg[base + 1 * D_DIM] = 0.f;
                        a2 = g_agg[base + 2 * D_DIM]; g_agg[base + 2 * D_DIM] = 0.f;
                        a3 = g_agg[base + 3 * D_DIM]; g_agg[base + 3 * D_DIM] = 0.f;
                    }
                    float x0 = lb, x1 = lb, x2 = lb, x3 = lb;
#pragma unroll
                    for (int k = 0; k < D_DIM; ++k) {
                        float w = s_WT[k * D_DIM + lane];
                        x0 = fmaf(__shfl_sync(0xffffffffu, a0, k), w, x0);
                        x1 = fmaf(__shfl_sync(0xffffffffu, a1, k), w, x1);
                        x2 = fmaf(__shfl_sync(0xffffffffu, a2, k), w, x2);
                        x3 = fmaf(__shfl_sync(0xffffffffu, a3, k), w, x3);
                    }
                    unsigned bm[4];
                    float xs[4] = {x0, x1, x2, x3};
#pragma unroll
                    for (int b = 0; b < B_Q; ++b) {
                        float c = g_c[base + b * D_DIM] * DECAY + xs[b];
                        float v = g_v[base + b * D_DIM] * DECAY + c;
                        bool sp = (v - VTH) >= 0.f;
                        g_c[base + b * D_DIM] = c;
                        g_v[base + b * D_DIM] = sp ? 0.f : v;
                        bm[b] = __ballot_sync(0xffffffffu, sp);
                    }
                    if (lane == 0) {
                        *reinterpret_cast<uint4*>(g_smask + (size_t)t * (N_NODES * B_Q) + n * B_Q) =
                            make_uint4(bm[0], bm[1], bm[2], bm[3]);
                        if (bm[0] | bm[1] | bm[2] | bm[3]) atomicAdd(&s_fcur, 1);
                    }
                }
                __syncthreads();
                if (tid == 0) { s_fprev = s_fcur; s_fcur = 0; }
                __syncthreads();
            }
            if (tid == 0) {
                g_hot_count = s_hot;
                __threadfence();
                atomicExch(&g_sim_done, 1);
            }
        }
        // all blocks wait for sim completion
        if (tid == 0) {
            while (atomicAdd(&g_sim_done, 0) == 0) __nanosleep(32);
        }
        __syncthreads();
    }

    // ================= score: warp per (b,k) pair (16*8 = 128 exactly) =================
    {
        int p = bid * NW + warp;
        int b = p >> 5;                      // K_T == 32
        float e = 0.f;
        if (read_masks) {
            int tn = __ldg(t_index + p);
            float w = 1.0f;
#pragma unroll
            for (int t = 0; t < T_STEPS; ++t) {
                unsigned m = __ldcg(&g_smask[(size_t)t * (N_NODES * B_Q) + tn * B_Q + b]);
                if ((m >> lane) & 1u) e += w;
                w *= RATIO;
            }
        }
        float f0 = e / NSCALE;
        float f1 = s_q[b * D_DIM + lane];
        float acc0 = s_b1[lane], acc1 = s_b1[lane + 32];
#pragma unroll
        for (int i = 0; i < 32; ++i) {
            float a = __shfl_sync(0xffffffffu, f0, i);
            float c = __shfl_sync(0xffffffffu, f1, i);
            acc0 = fmaf(a, s_W1[lane * 65 + i],              acc0);
            acc0 = fmaf(c, s_W1[lane * 65 + 32 + i],         acc0);
            acc1 = fmaf(a, s_W1[(lane + 32) * 65 + i],       acc1);
            acc1 = fmaf(c, s_W1[(lane + 32) * 65 + 32 + i],  acc1);
        }
        float h = fmaxf(acc0, 0.f) * s_W2[lane] + fmaxf(acc1, 0.f) * s_W2[lane + 32];
#pragma unroll
        for (int off = 16; off; off >>= 1)
            h += __shfl_down_sync(0xffffffffu, h, off);
        if (lane == 0) out[p] = h + s_b2s;
    }

    // ================= slow path only: cleanup handshake =================
    if (read_masks) {
        __syncthreads();
        if (tid == 0) {
            __threadfence();
            s_rank = atomicAdd(&g_score_done, 1);
        }
        __syncthreads();
        if (s_rank == NBLKS - 1) {
            int nh = g_hot_count;
            for (int i = warp; i < nh; i += NW) {
                int n = g_hot_list[i];
                size_t base = (size_t)(n * B_Q) * D_DIM + lane;
#pragma unroll
                for (int b = 0; b < B_Q; ++b) {
                    g_v[base + b * D_DIM]   = 0.f;
                    g_c[base + b * D_DIM]   = 0.f;
                    g_agg[base + b * D_DIM] = 0.f;
                }
                if (lane < T_STEPS)
                    *reinterpret_cast<uint4*>(g_smask + (size_t)lane * (N_NODES * B_Q) + n * B_Q) =
                        make_uint4(0u, 0u, 0u, 0u);
                if (lane == 0) g_hot_flag[n] = 0;
            }
            __syncthreads();
            if (tid == 0) {
                g_score_done = 0;
                __threadfence();
                atomicExch(&g_sim_done, 0);
            }
        }
    }
}

// ---------------- launch ----------------
extern "C" void kernel_launch(void* const* d_in, const int* in_sizes, int n_in,
                              void* d_out, int out_size) {
    fused_kernel<<<NBLKS, NTHR>>>(
        (const int*)d_in[0], (const int*)d_in[1], (const int*)d_in[2],
        (const int*)d_in[3], (const int*)d_in[4], (const int*)d_in[5],
        (const float*)d_in[6], (const float*)d_in[7], (const float*)d_in[8],
        (const float*)d_in[9], (const float*)d_in[10],
        (const float*)d_in[11], (const float*)d_in[12],
        (const float*)d_in[13], (const float*)d_in[14],
        (float*)d_out);
}

// round 9
// speedup vs baseline: 6.7202x; 1.1451x over previous
#include <cuda_runtime.h>

// ---------------- static problem sizes ----------------
#define N_NODES 20000
#define E_EDGES 320000
#define B_Q 4
#define K_T 32
#define D_DIM 32
#define DR_REL 40
#define T_STEPS 10
#define VTH 2.0f
#define DECAY 0.7788007830714049f   // exp(-1/4)
#define RATIO 0.95f
#define NSCALE 8.025261215232422f   // (1 - 0.95^10) / (1 - 0.95)

#define NBLKS 16
#define NTHR 256
#define NW 8                         // warps per block

// ---------------- persistent state (zero-init; cleanup restores zeros) ----------------
// Fast path touches NONE of these.
__device__ unsigned g_smask[T_STEPS * N_NODES * B_Q];
__device__ float    g_v[N_NODES * B_Q * D_DIM];
__device__ float    g_c[N_NODES * B_Q * D_DIM];
__device__ float    g_agg[N_NODES * B_Q * D_DIM];
__device__ int      g_hot_flag[N_NODES];
__device__ int      g_hot_list[N_NODES];
__device__ int      g_hot_count;
__device__ float    g_wrel[B_Q * DR_REL * D_DIM];
__device__ int      g_sim_done;     // slow path only
__device__ int      g_score_done;   // slow path only

__global__ __launch_bounds__(NTHR, 1)
void fused_kernel(const int* __restrict__ edge_src,
                  const int* __restrict__ edge_dst,
                  const int* __restrict__ edge_type,
                  const int* __restrict__ h_index,
                  const int* __restrict__ t_index,
                  const int* __restrict__ r_index,
                  const float* __restrict__ query_emb,
                  const float* __restrict__ relw_W,
                  const float* __restrict__ relw_b,
                  const float* __restrict__ lin_W,
                  const float* __restrict__ lin_b,
                  const float* __restrict__ W1,
                  const float* __restrict__ b1,
                  const float* __restrict__ W2,
                  const float* __restrict__ b2,
                  float* __restrict__ out) {
    __shared__ float s_qe[DR_REL * D_DIM];   // full query_emb table (5 KB)
    __shared__ float s_W1[64 * 65];          // padded row-major W1 (conflict-free)
    __shared__ float s_WT[D_DIM * D_DIM];    // lin_W^T (slow path only)
    __shared__ float s_q[B_Q * D_DIM];
    __shared__ float s_b1[64], s_W2[64];
    __shared__ float s_score[B_Q];
    __shared__ float s_b2s;
    __shared__ int   s_r[B_Q];
    __shared__ int   s_ts, s_hot, s_fprev, s_fcur, s_wrel_done, s_rank;

    const int tid  = threadIdx.x;
    const int lane = tid & 31;
    const int warp = tid >> 5;
    const int bid  = blockIdx.x;

    // ---------- W1 preload helper ----------
    auto preload_W1 = [&]() {
        const float4* W14 = reinterpret_cast<const float4*>(W1);
#pragma unroll
        for (int q = 0; q < 4; ++q) {
            int idx4 = q * NTHR + tid;          // 1024 float4 total
            float4 v = __ldg(W14 + idx4);
            float* dst = s_W1 + (idx4 >> 4) * 65 + ((idx4 & 15) << 2);
            dst[0] = v.x; dst[1] = v.y; dst[2] = v.z; dst[3] = v.w;
        }
    };

    // ---------- all loads issued in parallel (no dependent chains) ----------
    {
        const float4* qe4 = reinterpret_cast<const float4*>(query_emb);
        float4* sqe4 = reinterpret_cast<float4*>(s_qe);
        for (int i = tid; i < (DR_REL * D_DIM) / 4; i += NTHR)   // 320 float4
            sqe4[i] = __ldg(qe4 + i);
    }
    if (tid < B_Q) s_r[tid] = __ldg(r_index + tid);
    if (tid < 64) { s_b1[tid] = __ldg(b1 + tid); s_W2[tid] = __ldg(W2 + tid); }
    if (tid == 0) {
        s_b2s = __ldg(b2);
        s_ts = T_STEPS; s_hot = 0; s_fprev = 0; s_fcur = 0; s_wrel_done = 0;
    }
    if (bid == 0) preload_W1();              // block 0 needs W1 on both paths
    __syncthreads();

    if (tid < B_Q * D_DIM)
        s_q[tid] = s_qe[s_r[tid >> 5] * D_DIM + (tid & 31)];
    __syncthreads();

    // ---------- first-spike scan: c0 == 0 and x == 0 before any spike, so
    //            c stays 0 and v decays strictly -> spike only possible at t=0 ----------
    if (warp < B_Q) {
        float q = s_q[warp * D_DIM + lane];
        float boundary = q * (VTH * 0.5f) + VTH * 0.5f;
        unsigned m0 = __ballot_sync(0xffffffffu, (boundary - VTH) >= 0.f);
        if (lane == 0 && m0) s_ts = 0;       // race-free: only value ever written is 0
    }
    __syncthreads();
    const int ts = s_ts;                     // identical in every block

    // ======================= FAST PATH: no spikes ever =======================
    if (ts == T_STEPS) {
        if (bid != 0) return;                // 15 blocks retire immediately
        // Only 4 distinct scores (e == 0; feat = [0, query_b]); f0 terms vanish.
        if (warp < B_Q) {
            float f1 = s_q[warp * D_DIM + lane];
            float acc0 = s_b1[lane], acc1 = s_b1[lane + 32];
#pragma unroll
            for (int i = 0; i < 32; ++i) {
                float c = __shfl_sync(0xffffffffu, f1, i);
                acc0 = fmaf(c, s_W1[lane * 65 + 32 + i],        acc0);
                acc1 = fmaf(c, s_W1[(lane + 32) * 65 + 32 + i], acc1);
            }
            float h = fmaxf(acc0, 0.f) * s_W2[lane] + fmaxf(acc1, 0.f) * s_W2[lane + 32];
#pragma unroll
            for (int off = 16; off; off >>= 1)
                h += __shfl_down_sync(0xffffffffu, h, off);
            if (lane == 0) s_score[warp] = h + s_b2s;
        }
        __syncthreads();
        if (tid < B_Q * K_T) out[tid] = s_score[tid >> 5];
        return;
    }

    // ======================= SLOW PATH (spikes exist) =======================
    if (bid == 0) {
        // materialize head-node state at ts (ts == 0 here by the decay argument,
        // but keep the general roll loop)
        if (warp < B_Q) {
            int b = warp;
            int n = __ldg(h_index + b);
            float q = s_q[b * D_DIM + lane];
            float boundary = q * (VTH * 0.5f) + VTH * 0.5f;
            float v = boundary, c = 0.f;
            for (int t = 1; t <= ts; ++t) { c *= DECAY; v = v * DECAY + c; }
            bool sp = (v - VTH) >= 0.f;
            unsigned bm = __ballot_sync(0xffffffffu, sp);
            if (sp) v = 0.f;
            size_t base = (size_t)(n * B_Q + b) * D_DIM + lane;
            g_v[base] = v;
            g_c[base] = c;
            if (lane == 0) {
                if (bm) {
                    g_smask[(size_t)ts * (N_NODES * B_Q) + n * B_Q + b] = bm;
                    atomicAdd(&s_fprev, 1);
                }
                if (atomicExch(&g_hot_flag[n], 1) == 0) {
                    int p = atomicAdd(&s_hot, 1);
                    g_hot_list[p] = n;
                }
            }
        }
        for (int i = tid; i < D_DIM * D_DIM; i += NTHR) {
            int ii = i >> 5, j = i & 31;
            s_WT[i] = lin_W[j * D_DIM + ii];
        }
        __syncthreads();

        const float lb = __ldg(lin_b + lane);
        for (int t = ts + 1; t < T_STEPS; ++t) {
            int fc = s_fprev;
            if (fc != 0) {
                if (!s_wrel_done) {
                    for (int id = tid; id < B_Q * DR_REL * D_DIM; id += NTHR) {
                        int b  = id / (DR_REL * D_DIM);
                        int rd = id % (DR_REL * D_DIM);
                        float acc = relw_b[rd];
#pragma unroll
                        for (int i = 0; i < D_DIM; ++i)
                            acc += s_q[b * D_DIM + i] * relw_W[i * (DR_REL * D_DIM) + rd];
                        g_wrel[id] = acc;
                    }
                    __syncthreads();
                    if (tid == 0) s_wrel_done = 1;
                }
                const unsigned* mp = g_smask + (size_t)(t - 1) * (N_NODES * B_Q);
                for (int e = warp; e < E_EDGES; e += NW) {
                    int src = __ldg(edge_src + e);
                    uint4 m = *reinterpret_cast<const uint4*>(mp + src * 4);
                    if (m.x | m.y | m.z | m.w) {
                        int dst = __ldg(edge_dst + e);
                        int ty  = __ldg(edge_type + e);
                        if (lane == 0) {
                            if (atomicExch(&g_hot_flag[dst], 1) == 0) {
                                int p = atomicAdd(&s_hot, 1);
                                g_hot_list[p] = dst;
                            }
                        }
                        int off = ty * D_DIM + lane;
                        float* ag = g_agg + (size_t)(dst * B_Q) * D_DIM + lane;
                        if ((m.x >> lane) & 1u) atomicAdd(ag + 0 * D_DIM, g_wrel[0 * DR_REL * D_DIM + off]);
                        if ((m.y >> lane) & 1u) atomicAdd(ag + 1 * D_DIM, g_wrel[1 * DR_REL * D_DIM + off]);
                        if ((m.z >> lane) & 1u) atomicAdd(ag + 2 * D_DIM, g_wrel[2 * DR_REL * D_DIM + off]);
                        if ((m.w >> lane) & 1u) atomicAdd(ag + 3 * D_DIM, g_wrel[3 * DR_REL * D_DIM + off]);
                    }
                }
                __syncthreads();
            }
            int nh = s_hot;
            for (int i = warp; i < nh; i += NW) {
                int n = g_hot_list[i];
                size_t base = (size_t)(n * B_Q) * D_DIM + lane;
                float a0 = 0.f, a1 = 0.f, a2 = 0.f, a3 = 0.f;
                if (fc != 0) {
                    a0 = g_agg[base + 0 * D_DIM]; g_agg[base + 0 * D_DIM] = 0.f;
                    a1 = g_agg[base + 1 * D_DIM]; g_agg[base + 1 * D_DIM] = 0.f;
                    a2 = g_agg[base + 2 * D_DIM]; g_agg[base + 2 * D_DIM] = 0.f;
                    a3 = g_agg[base + 3 * D_DIM]; g_agg[base + 3 * D_DIM] = 0.f;
                }
                float x0 = lb, x1 = lb, x2 = lb, x3 = lb;
#pragma unroll
                for (int k = 0; k < D_DIM; ++k) {
                    float w = s_WT[k * D_DIM + lane];
                    x0 = fmaf(__shfl_sync(0xffffffffu, a0, k), w, x0);
                    x1 = fmaf(__shfl_sync(0xffffffffu, a1, k), w, x1);
                    x2 = fmaf(__shfl_sync(0xffffffffu, a2, k), w, x2);
                    x3 = fmaf(__shfl_sync(0xffffffffu, a3, k), w, x3);
                }
                unsigned bm[4];
                float xs[4] = {x0, x1, x2, x3};
#pragma unroll
                for (int b = 0; b < B_Q; ++b) {
                    float c = g_c[base + b * D_DIM] * DECAY + xs[b];
                    float v = g_v[base + b * D_DIM] * DECAY + c;
                    bool sp = (v - VTH) >= 0.f;
                    g_c[base + b * D_DIM] = c;
                    g_v[base + b * D_DIM] = sp ? 0.f : v;
                    bm[b] = __ballot_sync(0xffffffffu, sp);
                }
                if (lane == 0) {
                    *reinterpret_cast<uint4*>(g_smask + (size_t)t * (N_NODES * B_Q) + n * B_Q) =
                        make_uint4(bm[0], bm[1], bm[2], bm[3]);
                    if (bm[0] | bm[1] | bm[2] | bm[3]) atomicAdd(&s_fcur, 1);
                }
            }
            __syncthreads();
            if (tid == 0) { s_fprev = s_fcur; s_fcur = 0; }
            __syncthreads();
        }
        if (tid == 0) {
            g_hot_count = s_hot;
            __threadfence();
            atomicExch(&g_sim_done, 1);
        }
    } else {
        preload_W1();                        // overlap W1 load with block 0's sim
    }

    // wait for sim completion
    if (tid == 0) {
        while (atomicAdd(&g_sim_done, 0) == 0) __nanosleep(32);
    }
    __syncthreads();

    // full score: warp per (b,k) pair (16*8 = 128 exactly)
    {
        int p = bid * NW + warp;
        int b = p >> 5;                      // K_T == 32
        int tn = __ldg(t_index + p);
        float e = 0.f, w = 1.0f;
#pragma unroll
        for (int t = 0; t < T_STEPS; ++t) {
            unsigned m = __ldcg(&g_smask[(size_t)t * (N_NODES * B_Q) + tn * B_Q + b]);
            if ((m >> lane) & 1u) e += w;
            w *= RATIO;
        }
        float f0 = e / NSCALE;
        float f1 = s_q[b * D_DIM + lane];
        float acc0 = s_b1[lane], acc1 = s_b1[lane + 32];
#pragma unroll
        for (int i = 0; i < 32; ++i) {
            float a = __shfl_sync(0xffffffffu, f0, i);
            float c = __shfl_sync(0xffffffffu, f1, i);
            acc0 = fmaf(a, s_W1[lane * 65 + i],              acc0);
            acc0 = fmaf(c, s_W1[lane * 65 + 32 + i],         acc0);
            acc1 = fmaf(a, s_W1[(lane + 32) * 65 + i],       acc1);
            acc1 = fmaf(c, s_W1[(lane + 32) * 65 + 32 + i],  acc1);
        }
        float h = fmaxf(acc0, 0.f) * s_W2[lane] + fmaxf(acc1, 0.f) * s_W2[lane + 32];
#pragma unroll
        for (int off = 16; off; off >>= 1)
            h += __shfl_down_sync(0xffffffffu, h, off);
        if (lane == 0) out[p] = h + s_b2s;
    }

    // cleanup handshake (slow path only)
    __syncthreads();
    if (tid == 0) {
        __threadfence();
        s_rank = atomicAdd(&g_score_done, 1);
    }
    __syncthreads();
    if (s_rank == NBLKS - 1) {
        int nh = g_hot_count;
        for (int i = warp; i < nh; i += NW) {
            int n = g_hot_list[i];
            size_t base = (size_t)(n * B_Q) * D_DIM + lane;
#pragma unroll
            for (int b = 0; b < B_Q; ++b) {
                g_v[base + b * D_DIM]   = 0.f;
                g_c[base + b * D_DIM]   = 0.f;
                g_agg[base + b * D_DIM] = 0.f;
            }
            if (lane < T_STEPS)
                *reinterpret_cast<uint4*>(g_smask + (size_t)lane * (N_NODES * B_Q) + n * B_Q) =
                    make_uint4(0u, 0u, 0u, 0u);
            if (lane == 0) g_hot_flag[n] = 0;
        }
        __syncthreads();
        if (tid == 0) {
            g_score_done = 0;
            __threadfence();
            atomicExch(&g_sim_done, 0);
        }
    }
}

// ---------------- launch ----------------
extern "C" void kernel_launch(void* const* d_in, const int* in_sizes, int n_in,
                              void* d_out, int out_size) {
    fused_kernel<<<NBLKS, NTHR>>>(
        (const int*)d_in[0], (const int*)d_in[1], (const int*)d_in[2],
        (const int*)d_in[3], (const int*)d_in[4], (const int*)d_in[5],
        (const float*)d_in[6], (const float*)d_in[7], (const float*)d_in[8],
        (const float*)d_in[9], (const float*)d_in[10],
        (const float*)d_in[11], (const float*)d_in[12],
        (const float*)d_in[13], (const float*)d_in[14],
        (float*)d_out);
}